// round 9
// baseline (speedup 1.0000x reference)
#include <cuda_runtime.h>
#include <stdint.h>

// Inputs (metadata order):
//  0: vertex_dofs  [V,1]  f32
//  1: edge_dofs    [E,2]  f32
//  2: face_dofs    [C,1]  f32
//  3: y            [C,10,16] f32
//  4: faces        [C,3]  i32
//  5: faces_to_edges [C,3] i32
//  6: edge_orientation [C,3] i32
// Output: [C,16] f32

#define NB 10
#define QPTS 16
#define THREADS 256
#define BLOCKS_PER_SM 6   // <=42 regs -> 48 warps/SM cap (75%)

__global__ __launch_bounds__(THREADS, BLOCKS_PER_SM)
void quadfn_kernel(const float* __restrict__ vertex_dofs,
                   const float* __restrict__ edge_dofs,
                   const float* __restrict__ face_dofs,
                   const float* __restrict__ y,
                   const int*   __restrict__ faces,
                   const int*   __restrict__ f2e,
                   const int*   __restrict__ orient,
                   float*       __restrict__ out,
                   int C, int G)
{
    const int lane = threadIdx.x & 31;
    const int qg   = lane & 3;          // which float4 of Q=16
    const int grp  = lane & ~3;         // group base lane within warp
    const unsigned m = 0xffffffffu;

    const int g0 = (blockIdx.x * THREADS + threadIdx.x) >> 2;  // group id

    // Persistent grid-stride loop. NO cross-iteration pipelining: the R6
    // single-cell body, unchanged, so register pressure stays ~34-40 and
    // occupancy stays high. Persistence removes the per-CTA launch/drain
    // churn and prologue cost that capped R6's achieved occupancy at 64%.
    // Warp-uniform condition keeps the shuffles convergent at the tail.
    for (int c = g0; __any_sync(m, c < C); c += G) {
        const bool act = (c < C);

        // ---- streaming y tile: 10 independent LDG.128 in flight.
        // __ldcs = evict-first (zero reuse; keep L2 for the dof tables).
        float4 v[NB];
        if (act) {
            const float4* yv = reinterpret_cast<const float4*>(
                                   y + (size_t)c * NB * QPTS) + qg;
            #pragma unroll
            for (int b = 0; b < NB; b++)
                v[b] = __ldcs(yv + b * (QPTS / 4));
        }

        // ---- cooperative gather within the 4-lane group (no smem/barrier)
        float wv = 0.f, wa = 0.f, wb = 0.f, wf = 0.f;
        if (act) {
            if (qg < 3) {
                int vidx = __ldg(&faces[3 * c + qg]);
                int eidx = __ldg(&f2e[3 * c + qg]);
                int o    = __ldg(&orient[3 * c + qg]);
                wv = __ldg(&vertex_dofs[vidx]);
                float2 ed = __ldg((const float2*)edge_dofs + eidx);
                wa = (o != 0) ? ed.x : ed.y;
                wb = (o != 0) ? ed.y : ed.x;
            } else {
                wf = __ldg(&face_dofs[c]);
            }
        }

        // ---- broadcast the 10 weights across the group
        float w0 = __shfl_sync(m, wv, grp + 0);
        float w1 = __shfl_sync(m, wv, grp + 1);
        float w2 = __shfl_sync(m, wv, grp + 2);
        float w3 = __shfl_sync(m, wa, grp + 0);
        float w4 = __shfl_sync(m, wb, grp + 0);
        float w5 = __shfl_sync(m, wa, grp + 1);
        float w6 = __shfl_sync(m, wb, grp + 1);
        float w7 = __shfl_sync(m, wa, grp + 2);
        float w8 = __shfl_sync(m, wb, grp + 2);
        float w9 = __shfl_sync(m, wf, grp + 3);

        // ---- contraction + store
        if (act) {
            float4 acc;
            acc.x = w0 * v[0].x; acc.y = w0 * v[0].y;
            acc.z = w0 * v[0].z; acc.w = w0 * v[0].w;
            #define ACC(W, B)                       \
                acc.x = fmaf(W, v[B].x, acc.x);     \
                acc.y = fmaf(W, v[B].y, acc.y);     \
                acc.z = fmaf(W, v[B].z, acc.z);     \
                acc.w = fmaf(W, v[B].w, acc.w);
            ACC(w1, 1) ACC(w2, 2) ACC(w3, 3) ACC(w4, 4)
            ACC(w5, 5) ACC(w6, 6) ACC(w7, 7) ACC(w8, 8) ACC(w9, 9)
            #undef ACC
            __stcs(reinterpret_cast<float4*>(out + (size_t)c * QPTS) + qg, acc);
        }
    }
}

extern "C" void kernel_launch(void* const* d_in, const int* in_sizes, int n_in,
                              void* d_out, int out_size)
{
    const float* vertex_dofs = (const float*)d_in[0];
    const float* edge_dofs   = (const float*)d_in[1];
    const float* face_dofs   = (const float*)d_in[2];
    const float* y           = (const float*)d_in[3];
    const int*   faces       = (const int*)d_in[4];
    const int*   f2e         = (const int*)d_in[5];
    const int*   orient      = (const int*)d_in[6];
    float*       out         = (float*)d_out;

    // Derive C from y: [C, NB, Q]
    int C = in_sizes[3] / (NB * QPTS);

    int num_sms = 148;
    cudaDeviceGetAttribute(&num_sms, cudaDevAttrMultiProcessorCount, 0);

    int blocks = num_sms * BLOCKS_PER_SM;   // exact residency, persistent
    int G = blocks * (THREADS / 4);         // total 4-lane groups per stride

    quadfn_kernel<<<blocks, THREADS>>>(vertex_dofs, edge_dofs, face_dofs, y,
                                       faces, f2e, orient, out, C, G);
}

// round 10
// speedup vs baseline: 1.5092x; 1.5092x over previous
#include <cuda_runtime.h>
#include <stdint.h>

// Inputs (metadata order):
//  0: vertex_dofs  [V,1]  f32
//  1: edge_dofs    [E,2]  f32
//  2: face_dofs    [C,1]  f32
//  3: y            [C,10,16] f32
//  4: faces        [C,3]  i32
//  5: faces_to_edges [C,3] i32
//  6: edge_orientation [C,3] i32
// Output: [C,16] f32

#define NB 10
#define QPTS 16
#define THREADS 256  // 4 threads per cell, one float4 (4 quad pts) each

__global__ __launch_bounds__(THREADS)
void quadfn_kernel(const float* __restrict__ vertex_dofs,
                   const float* __restrict__ edge_dofs,
                   const float* __restrict__ face_dofs,
                   const float* __restrict__ y,
                   const int*   __restrict__ faces,
                   const int*   __restrict__ f2e,
                   const int*   __restrict__ orient,
                   float*       __restrict__ out,
                   int C)
{
    const int tid  = blockIdx.x * THREADS + threadIdx.x;
    const int c    = tid >> 2;          // one cell per 4-lane group
    const int lane = threadIdx.x & 31;
    const int qg   = lane & 3;          // which float4 of Q=16
    const int grp  = lane & ~3;         // group base lane within warp

    if (c >= C) return;                 // tail: whole 4-lane groups drop out

    // ---- Phase 0a: start the long gather chain FIRST. The idx->dof chain
    // is the block's critical path (~2 dependent memory hops); issuing the
    // index loads before the y burst starts the chain as early as possible.
    // Index arrays and face_dofs are read exactly once -> __ldcs
    // (evict-first) keeps L2 for the reused vertex/edge dof tables.
    int   vidx = 0, eidx = 0, o = 1;
    float wf = 0.f;
    if (qg < 3) {
        vidx = __ldcs(&faces[3 * c + qg]);
        eidx = __ldcs(&f2e[3 * c + qg]);
        o    = __ldcs(&orient[3 * c + qg]);
    } else {
        wf = __ldcs(&face_dofs[c]);
    }

    // ---- Phase 0b: streaming y tile: 10 independent LDG.128 in flight
    // across the rest of the gather chain. __ldcs = evict-first (zero reuse).
    float4 v[NB];
    {
        const float4* yv = reinterpret_cast<const float4*>(
                               y + (size_t)c * NB * QPTS) + qg;
        #pragma unroll
        for (int b = 0; b < NB; b++)
            v[b] = __ldcs(yv + b * (QPTS / 4));
    }

    // ---- Phase 1: dependent dof loads (indices are back; these hit L2).
    float wv = 0.f, wa = 0.f, wb = 0.f;
    if (qg < 3) {
        wv = __ldg(&vertex_dofs[vidx]);
        float2 ed = __ldg((const float2*)edge_dofs + eidx);
        wa = (o != 0) ? ed.x : ed.y;   // first edge dof
        wb = (o != 0) ? ed.y : ed.x;   // second edge dof
    }

    // ---- Phase 2: broadcast the 10 weights across the 4-lane group.
    const unsigned m = 0xffffffffu;
    float w0 = __shfl_sync(m, wv, grp + 0);
    float w1 = __shfl_sync(m, wv, grp + 1);
    float w2 = __shfl_sync(m, wv, grp + 2);
    float w3 = __shfl_sync(m, wa, grp + 0);
    float w4 = __shfl_sync(m, wb, grp + 0);
    float w5 = __shfl_sync(m, wa, grp + 1);
    float w6 = __shfl_sync(m, wb, grp + 1);
    float w7 = __shfl_sync(m, wa, grp + 2);
    float w8 = __shfl_sync(m, wb, grp + 2);
    float w9 = __shfl_sync(m, wf, grp + 3);

    // ---- Phase 3: contraction on the prefetched registers ----
    float4 acc;
    acc.x = w0 * v[0].x; acc.y = w0 * v[0].y;
    acc.z = w0 * v[0].z; acc.w = w0 * v[0].w;

    #define ACC(W, B)                         \
        acc.x = fmaf(W, v[B].x, acc.x);       \
        acc.y = fmaf(W, v[B].y, acc.y);       \
        acc.z = fmaf(W, v[B].z, acc.z);       \
        acc.w = fmaf(W, v[B].w, acc.w);
    ACC(w1, 1) ACC(w2, 2) ACC(w3, 3) ACC(w4, 4)
    ACC(w5, 5) ACC(w6, 6) ACC(w7, 7) ACC(w8, 8) ACC(w9, 9)
    #undef ACC

    __stcs(reinterpret_cast<float4*>(out + (size_t)c * QPTS) + qg, acc);
}

extern "C" void kernel_launch(void* const* d_in, const int* in_sizes, int n_in,
                              void* d_out, int out_size)
{
    const float* vertex_dofs = (const float*)d_in[0];
    const float* edge_dofs   = (const float*)d_in[1];
    const float* face_dofs   = (const float*)d_in[2];
    const float* y           = (const float*)d_in[3];
    const int*   faces       = (const int*)d_in[4];
    const int*   f2e         = (const int*)d_in[5];
    const int*   orient      = (const int*)d_in[6];
    float*       out         = (float*)d_out;

    // Derive C from y: [C, NB, Q]
    int C = in_sizes[3] / (NB * QPTS);

    int total_threads = C * 4;
    int blocks = (total_threads + THREADS - 1) / THREADS;
    quadfn_kernel<<<blocks, THREADS>>>(vertex_dofs, edge_dofs, face_dofs, y,
                                       faces, f2e, orient, out, C);
}

// round 11
// speedup vs baseline: 1.5676x; 1.0387x over previous
#include <cuda_runtime.h>
#include <stdint.h>

// Inputs (metadata order):
//  0: vertex_dofs  [V,1]  f32
//  1: edge_dofs    [E,2]  f32
//  2: face_dofs    [C,1]  f32
//  3: y            [C,10,16] f32
//  4: faces        [C,3]  i32
//  5: faces_to_edges [C,3] i32
//  6: edge_orientation [C,3] i32
// Output: [C,16] f32

#define NB 10
#define QPTS 16
#define THREADS 128  // 4 threads per cell; smaller blocks decorrelate
                     // warp-cohort phases across the SM

__global__ __launch_bounds__(THREADS)
void quadfn_kernel(const float* __restrict__ vertex_dofs,
                   const float* __restrict__ edge_dofs,
                   const float* __restrict__ face_dofs,
                   const float* __restrict__ y,
                   const int*   __restrict__ faces,
                   const int*   __restrict__ f2e,
                   const int*   __restrict__ orient,
                   float*       __restrict__ out,
                   int C)
{
    const int tid  = blockIdx.x * THREADS + threadIdx.x;
    const int c    = tid >> 2;          // one cell per 4-lane group
    const int lane = threadIdx.x & 31;
    const int qg   = lane & 3;          // which float4 of Q=16
    const int grp  = lane & ~3;         // group base lane within warp

    if (c >= C) return;                 // tail: whole 4-lane groups drop out

    // ---- Phase 0: streaming y tile first (R6 ordering — measured fastest).
    // 10 independent LDG.128 in flight across the gather chain.
    // __ldcs = evict-first: y has zero reuse; keep L2 for the dof tables.
    float4 v[NB];
    {
        const float4* yv = reinterpret_cast<const float4*>(
                               y + (size_t)c * NB * QPTS) + qg;
        #pragma unroll
        for (int b = 0; b < NB; b++)
            v[b] = __ldcs(yv + b * (QPTS / 4));
    }

    // ---- Phase 1: cooperative gather within the 4-lane group (no smem,
    // no __syncthreads — warps stay fully independent).
    float wv = 0.f, wa = 0.f, wb = 0.f, wf = 0.f;
    if (qg < 3) {
        int vidx = __ldg(&faces[3 * c + qg]);
        wv = __ldg(&vertex_dofs[vidx]);
        int    eidx = __ldg(&f2e[3 * c + qg]);
        int    o    = __ldg(&orient[3 * c + qg]);
        float2 ed   = __ldg((const float2*)edge_dofs + eidx);
        wa = (o != 0) ? ed.x : ed.y;   // first edge dof
        wb = (o != 0) ? ed.y : ed.x;   // second edge dof
    } else {
        wf = __ldg(&face_dofs[c]);
    }

    // ---- Phase 2: broadcast the 10 weights across the group via shuffle.
    const unsigned m = 0xffffffffu;
    float w0 = __shfl_sync(m, wv, grp + 0);
    float w1 = __shfl_sync(m, wv, grp + 1);
    float w2 = __shfl_sync(m, wv, grp + 2);
    float w3 = __shfl_sync(m, wa, grp + 0);
    float w4 = __shfl_sync(m, wb, grp + 0);
    float w5 = __shfl_sync(m, wa, grp + 1);
    float w6 = __shfl_sync(m, wb, grp + 1);
    float w7 = __shfl_sync(m, wa, grp + 2);
    float w8 = __shfl_sync(m, wb, grp + 2);
    float w9 = __shfl_sync(m, wf, grp + 3);

    // ---- Phase 3: contraction on the prefetched registers ----
    float4 acc;
    acc.x = w0 * v[0].x; acc.y = w0 * v[0].y;
    acc.z = w0 * v[0].z; acc.w = w0 * v[0].w;

    #define ACC(W, B)                         \
        acc.x = fmaf(W, v[B].x, acc.x);       \
        acc.y = fmaf(W, v[B].y, acc.y);       \
        acc.z = fmaf(W, v[B].z, acc.z);       \
        acc.w = fmaf(W, v[B].w, acc.w);
    ACC(w1, 1) ACC(w2, 2) ACC(w3, 3) ACC(w4, 4)
    ACC(w5, 5) ACC(w6, 6) ACC(w7, 7) ACC(w8, 8) ACC(w9, 9)
    #undef ACC

    __stcs(reinterpret_cast<float4*>(out + (size_t)c * QPTS) + qg, acc);
}

extern "C" void kernel_launch(void* const* d_in, const int* in_sizes, int n_in,
                              void* d_out, int out_size)
{
    const float* vertex_dofs = (const float*)d_in[0];
    const float* edge_dofs   = (const float*)d_in[1];
    const float* face_dofs   = (const float*)d_in[2];
    const float* y           = (const float*)d_in[3];
    const int*   faces       = (const int*)d_in[4];
    const int*   f2e         = (const int*)d_in[5];
    const int*   orient      = (const int*)d_in[6];
    float*       out         = (float*)d_out;

    // Derive C from y: [C, NB, Q]
    int C = in_sizes[3] / (NB * QPTS);

    int total_threads = C * 4;
    int blocks = (total_threads + THREADS - 1) / THREADS;
    quadfn_kernel<<<blocks, THREADS>>>(vertex_dofs, edge_dofs, face_dofs, y,
                                       faces, f2e, orient, out, C);
}

// round 12
// speedup vs baseline: 1.5990x; 1.0200x over previous
#include <cuda_runtime.h>
#include <stdint.h>

// Inputs (metadata order):
//  0: vertex_dofs  [V,1]  f32
//  1: edge_dofs    [E,2]  f32
//  2: face_dofs    [C,1]  f32
//  3: y            [C,10,16] f32
//  4: faces        [C,3]  i32
//  5: faces_to_edges [C,3] i32
//  6: edge_orientation [C,3] i32
// Output: [C,16] f32

#define NB 10
#define QPTS 16
#define THREADS 64   // 4 threads per cell; 2-warp blocks give the work
                     // distributor the finest grain for phase-decorrelating
                     // block starts across each SM (256->128 already helped)

__global__ __launch_bounds__(THREADS)
void quadfn_kernel(const float* __restrict__ vertex_dofs,
                   const float* __restrict__ edge_dofs,
                   const float* __restrict__ face_dofs,
                   const float* __restrict__ y,
                   const int*   __restrict__ faces,
                   const int*   __restrict__ f2e,
                   const int*   __restrict__ orient,
                   float*       __restrict__ out,
                   int C)
{
    const int tid  = blockIdx.x * THREADS + threadIdx.x;
    const int c    = tid >> 2;          // one cell per 4-lane group
    const int lane = threadIdx.x & 31;
    const int qg   = lane & 3;          // which float4 of Q=16
    const int grp  = lane & ~3;         // group base lane within warp

    if (c >= C) return;                 // tail: whole 4-lane groups drop out

    // ---- Phase 0: streaming y tile first (measured-fastest ordering).
    // 10 independent LDG.128 in flight across the gather chain.
    // __ldcs = evict-first: y has zero reuse; keep L2 for the dof tables.
    float4 v[NB];
    {
        const float4* yv = reinterpret_cast<const float4*>(
                               y + (size_t)c * NB * QPTS) + qg;
        #pragma unroll
        for (int b = 0; b < NB; b++)
            v[b] = __ldcs(yv + b * (QPTS / 4));
    }

    // ---- Phase 1: cooperative gather within the 4-lane group (no smem,
    // no __syncthreads — warps stay fully independent).
    float wv = 0.f, wa = 0.f, wb = 0.f, wf = 0.f;
    if (qg < 3) {
        int vidx = __ldg(&faces[3 * c + qg]);
        wv = __ldg(&vertex_dofs[vidx]);
        int    eidx = __ldg(&f2e[3 * c + qg]);
        int    o    = __ldg(&orient[3 * c + qg]);
        float2 ed   = __ldg((const float2*)edge_dofs + eidx);
        wa = (o != 0) ? ed.x : ed.y;   // first edge dof
        wb = (o != 0) ? ed.y : ed.x;   // second edge dof
    } else {
        wf = __ldg(&face_dofs[c]);
    }

    // ---- Phase 2: broadcast the 10 weights across the group via shuffle.
    const unsigned m = 0xffffffffu;
    float w0 = __shfl_sync(m, wv, grp + 0);
    float w1 = __shfl_sync(m, wv, grp + 1);
    float w2 = __shfl_sync(m, wv, grp + 2);
    float w3 = __shfl_sync(m, wa, grp + 0);
    float w4 = __shfl_sync(m, wb, grp + 0);
    float w5 = __shfl_sync(m, wa, grp + 1);
    float w6 = __shfl_sync(m, wb, grp + 1);
    float w7 = __shfl_sync(m, wa, grp + 2);
    float w8 = __shfl_sync(m, wb, grp + 2);
    float w9 = __shfl_sync(m, wf, grp + 3);

    // ---- Phase 3: contraction on the prefetched registers ----
    float4 acc;
    acc.x = w0 * v[0].x; acc.y = w0 * v[0].y;
    acc.z = w0 * v[0].z; acc.w = w0 * v[0].w;

    #define ACC(W, B)                         \
        acc.x = fmaf(W, v[B].x, acc.x);       \
        acc.y = fmaf(W, v[B].y, acc.y);       \
        acc.z = fmaf(W, v[B].z, acc.z);       \
        acc.w = fmaf(W, v[B].w, acc.w);
    ACC(w1, 1) ACC(w2, 2) ACC(w3, 3) ACC(w4, 4)
    ACC(w5, 5) ACC(w6, 6) ACC(w7, 7) ACC(w8, 8) ACC(w9, 9)
    #undef ACC

    __stcs(reinterpret_cast<float4*>(out + (size_t)c * QPTS) + qg, acc);
}

extern "C" void kernel_launch(void* const* d_in, const int* in_sizes, int n_in,
                              void* d_out, int out_size)
{
    const float* vertex_dofs = (const float*)d_in[0];
    const float* edge_dofs   = (const float*)d_in[1];
    const float* face_dofs   = (const float*)d_in[2];
    const float* y           = (const float*)d_in[3];
    const int*   faces       = (const int*)d_in[4];
    const int*   f2e         = (const int*)d_in[5];
    const int*   orient      = (const int*)d_in[6];
    float*       out         = (float*)d_out;

    // Derive C from y: [C, NB, Q]
    int C = in_sizes[3] / (NB * QPTS);

    int total_threads = C * 4;
    int blocks = (total_threads + THREADS - 1) / THREADS;
    quadfn_kernel<<<blocks, THREADS>>>(vertex_dofs, edge_dofs, face_dofs, y,
                                       faces, f2e, orient, out, C);
}